// round 13
// baseline (speedup 1.0000x reference)
#include <cuda_runtime.h>
#include <cuda_fp16.h>
#include <cstdint>

// ---------------- problem constants ----------------
#define BB 8
#define CC 256
#define HHW 6400          // 80*80
#define GROUPS 32
#define CPG 8
#define TOTAL (BB*CC*HHW) // 13,107,200
#define PW 82
#define PHW (PW*PW)       // 6724
#define NCHUNK 36         // K chunks of 64: tap t = ch>>2, ci0 = (ch&3)*64
#define NSTG 3            // cp.async pipeline stages
#define STAGE 32768       // bytes per stage: A 16KB + B 16KB

// ---------------- scratch (__device__ globals; no allocation) ----------------
__device__ __half g_padh[(size_t)BB * PHW * CC];     // channels-last padded input, fp16
__device__ uint2  g_wtH[(size_t)2 * NCHUNK * 2048];  // weights fp16 fragment-linear
__device__ float  g_h[(size_t)TOTAL];                // conv output, NCHW fp32
__device__ float  g_gate[BB*HHW];
__device__ float  g_mean[BB*GROUPS];
__device__ float  g_rstd[BB*GROUPS];

// ---------------- helpers ----------------
__device__ __forceinline__ void mma_f16(float* d, const uint32_t* a, const uint32_t* b){
    asm volatile(
        "mma.sync.aligned.m16n8k16.row.col.f32.f16.f16.f32 "
        "{%0,%1,%2,%3}, {%4,%5,%6,%7}, {%8,%9}, {%0,%1,%2,%3};"
        : "+f"(d[0]), "+f"(d[1]), "+f"(d[2]), "+f"(d[3])
        : "r"(a[0]), "r"(a[1]), "r"(a[2]), "r"(a[3]), "r"(b[0]), "r"(b[1]));
}
__device__ __forceinline__ void cp_async16(uint32_t dst, const void* src){
    asm volatile("cp.async.cg.shared.global [%0], [%1], 16;" :: "r"(dst), "l"(src));
}
__device__ __forceinline__ void ldmatrix4(uint32_t* r, uint32_t addr){
    asm volatile("ldmatrix.sync.aligned.m8n8.x4.shared.b16 {%0,%1,%2,%3}, [%4];"
        : "=r"(r[0]), "=r"(r[1]), "=r"(r[2]), "=r"(r[3]) : "r"(addr));
}

// ---------------- prep kernels ----------------
// weights -> fp16 B-fragment-linear per (half, chunk of 64 k):
//   uint2 entry idx = ((half*NCHUNK+ch)*2048) + (nt*4+kt)*32 + lane
//   co = half*128 + nt*8 + lane/4 ; t = ch>>2 ; kb = (ch&3)*64 + kt*16 + 2*(lane%4)
//   x = {W[co][kb][t], W[co][kb+1][t]}, y = {W[co][kb+8][t], W[co][kb+9][t]}
__global__ __launch_bounds__(256)
void prep_w_kernel(const float* __restrict__ w, uint2* __restrict__ wtH)
{
    int i = blockIdx.x * 256 + threadIdx.x;
    if (i >= 2 * NCHUNK * 2048) return;
    int lane = i & 31;
    int kt   = (i >> 5) & 3;
    int nt   = (i >> 7) & 15;
    int rest = i >> 11;                 // half*NCHUNK + ch
    int ch   = rest % NCHUNK;
    int half = rest / NCHUNK;
    int co = half * 128 + nt * 8 + (lane >> 2);
    int t  = ch >> 2;
    int kb = (ch & 3) * 64 + kt * 16 + 2 * (lane & 3);
    const float* wp = w + (size_t)co * CC * 9 + t;
    __half2 lo = __halves2half2(__float2half_rn(wp[(size_t)(kb    ) * 9]),
                                __float2half_rn(wp[(size_t)(kb + 1) * 9]));
    __half2 hi = __halves2half2(__float2half_rn(wp[(size_t)(kb + 8) * 9]),
                                __float2half_rn(wp[(size_t)(kb + 9) * 9]));
    uint2 v;
    v.x = *(uint32_t*)&lo;
    v.y = *(uint32_t*)&hi;
    wtH[i] = v;
}

__global__ __launch_bounds__(256)
void zero_border_kernel(__half* __restrict__ pad)
{
    int pos = blockIdx.x;       // 0..81
    int s   = blockIdx.y;
    int b   = blockIdx.z;
    int py, px;
    if (s == 0)      { py = 0;   px = pos; }
    else if (s == 1) { py = 81;  px = pos; }
    else if (s == 2) { py = pos; px = 0;   }
    else             { py = pos; px = 81;  }
    pad[((size_t)b * PHW + py * PW + px) * CC + threadIdx.x] = __float2half_rn(0.0f);
}

// NCHW x -> channels-last padded fp16 (smem transpose, one row x 32ci per block)
__global__ __launch_bounds__(256)
void pad_x_t_kernel(const float* __restrict__ x, __half* __restrict__ pad)
{
    __shared__ float t[32 * 81];
    const int y   = blockIdx.x;
    const int cB  = blockIdx.y;
    const int b   = blockIdx.z;
    const int tid = threadIdx.x;
    for (int idx = tid; idx < 2560; idx += 256) {
        int px = idx % 80, cc = idx / 80;
        t[cc * 81 + px] = x[((size_t)(b * CC + cB * 32 + cc) * 80 + y) * 80 + px];
    }
    __syncthreads();
    for (int idx = tid; idx < 2560; idx += 256) {
        int cc = idx & 31, px = idx >> 5;
        pad[((size_t)b * PHW + (y + 1) * PW + (px + 1)) * CC + cB * 32 + cc] =
            __float2half_rn(t[cc * 81 + px]);
    }
}

// NCHW h -> GN affine + ReLU -> channels-last padded fp16
__global__ __launch_bounds__(256)
void pad_h_t_kernel(const float* __restrict__ h, const float* __restrict__ mean,
                    const float* __restrict__ rstd, const float* __restrict__ gw,
                    const float* __restrict__ gb, __half* __restrict__ pad)
{
    __shared__ float t[32 * 81];
    __shared__ float ssc[32], ssb[32];
    const int y   = blockIdx.x;
    const int cB  = blockIdx.y;
    const int b   = blockIdx.z;
    const int tid = threadIdx.x;
    if (tid < 32) {
        int ci = cB * 32 + tid;
        int bg = b * GROUPS + ci / CPG;
        float sc = rstd[bg] * gw[ci];
        ssc[tid] = sc;
        ssb[tid] = fmaf(-mean[bg], sc, gb[ci]);
    }
    for (int idx = tid; idx < 2560; idx += 256) {
        int px = idx % 80, cc = idx / 80;
        t[cc * 81 + px] = h[((size_t)(b * CC + cB * 32 + cc) * 80 + y) * 80 + px];
    }
    __syncthreads();
    for (int idx = tid; idx < 2560; idx += 256) {
        int cc = idx & 31, px = idx >> 5;
        float v = fmaxf(fmaf(t[cc * 81 + px], ssc[cc], ssb[cc]), 0.0f);
        pad[((size_t)b * PHW + (y + 1) * PW + (px + 1)) * CC + cB * 32 + cc] =
            __float2half_rn(v);
    }
}

// ---------------- fp16 HMMA implicit-GEMM conv, cp.async 3-stage, chunk=64 ----------------
// 256 thr = 8 warps (2M x 4N), warp tile 64px x 32co. CTA tile 128px x 128co.
// Pixel tile 16 rows x 8 cols. K chunk = 64 (one tap, 64 contiguous ci).
// Stage: A plane-major [kk(8)][px(128)][16B] 16KB + B fragment-linear 16KB.
__global__ __launch_bounds__(256, 2)
void conv_mma_kernel(const __half* __restrict__ pad, const uint2* __restrict__ wtH,
                     float* __restrict__ out)
{
    extern __shared__ char dsm[];
    __shared__ int s_toff[9];

    const int tid  = threadIdx.x;
    const int lane = tid & 31;
    const int warp = tid >> 5;               // 0..7
    const int mw = warp >> 2;                // 0..1
    const int nw = warp & 3;                 // 0..3

    if (tid < 9) s_toff[tid] = ((tid / 3) * PW + (tid % 3)) * CC;

    const int PX0 = blockIdx.x * 8;
    const int PY0 = blockIdx.y * 16;
    const int bz  = blockIdx.z;
    const int b   = bz >> 1;
    const int half = bz & 1;
    const int co0  = half * 128;

    // producer: thread covers pixel pxP = tid>>1, k-half segH = tid&1
    const int pxP  = tid >> 1;
    const int segH = tid & 1;
    const int gy = PY0 + (pxP >> 3);
    const int gx = PX0 + (pxP & 7);
    const __half* Apix = pad + ((size_t)b * PHW + (size_t)gy * PW + gx) * CC;
    const char* Bsrc0 = (const char*)(wtH + (size_t)half * NCHUNK * 2048);
    const uint32_t smem0 = (uint32_t)__cvta_generic_to_shared(dsm);

    // consumer ldmatrix lane address part: tile t = lane>>3, row = lane&7
    const int ltile = lane >> 3;
    const uint32_t lmLane = (uint32_t)((ltile >> 1) * 2048 +
                                       (((ltile & 1) * 8 + (lane & 7)) * 16));

    float acc[4][4][4];
#pragma unroll
    for (int mi = 0; mi < 4; mi++)
#pragma unroll
        for (int ni = 0; ni < 4; ni++)
#pragma unroll
            for (int q = 0; q < 4; q++) acc[mi][ni][q] = 0.0f;

    __syncthreads();   // s_toff ready

#define ISSUE(CH) do {                                                          \
        const int _ch = (CH);                                                   \
        const int _st = _ch % NSTG;                                             \
        const __half* _as = Apix + s_toff[_ch >> 2] + ((_ch & 3) << 6);         \
        uint32_t _base = smem0 + _st * STAGE;                                   \
        _Pragma("unroll")                                                       \
        for (int _j = 0; _j < 4; _j++) {                                        \
            int _kk = segH * 4 + _j;                                            \
            cp_async16(_base + _kk * 2048 + pxP * 16, _as + _kk * 8);           \
        }                                                                       \
        const char* _bs = Bsrc0 + (size_t)_ch * 16384 + tid * 64;               \
        uint32_t _bd = _base + 16384 + tid * 64;                                \
        _Pragma("unroll")                                                       \
        for (int _j = 0; _j < 4; _j++)                                          \
            cp_async16(_bd + _j * 16, _bs + _j * 16);                           \
        asm volatile("cp.async.commit_group;" ::: "memory");                    \
    } while (0)

    // prologue: stages 0,1
    ISSUE(0);
    ISSUE(1);

    for (int ch = 0; ch < NCHUNK; ch++) {
        if (ch < NCHUNK - 1)
            asm volatile("cp.async.wait_group 1;" ::: "memory");
        else
            asm volatile("cp.async.wait_group 0;" ::: "memory");
        __syncthreads();

        const int st = ch % NSTG;
        const uint32_t Abase = smem0 + st * STAGE;
        const uint2* Bs = (const uint2*)(dsm + st * STAGE + 16384);

#pragma unroll
        for (int kt = 0; kt < 4; kt++) {
            uint32_t af[4][4];
            uint2 bf[4];
            const uint32_t kbase = Abase + kt * 4096 + lmLane;
#pragma unroll
            for (int mi = 0; mi < 4; mi++)
                ldmatrix4(af[mi], kbase + (uint32_t)((mw * 64 + mi * 16) * 16));
#pragma unroll
            for (int ni = 0; ni < 4; ni++)
                bf[ni] = Bs[((nw * 4 + ni) * 4 + kt) * 32 + lane];
#pragma unroll
            for (int mi = 0; mi < 4; mi++)
#pragma unroll
                for (int ni = 0; ni < 4; ni++)
                    mma_f16(acc[mi][ni], af[mi], (const uint32_t*)&bf[ni]);
        }

        if (ch + 2 < NCHUNK) ISSUE(ch + 2);
    }
#undef ISSUE

    // ---- epilogue: acc -> out[b][co][py][px] (NCHW) ----
    const int r0 = lane >> 2;
    const int c0 = 2 * (lane & 3);
#pragma unroll
    for (int mi = 0; mi < 4; mi++) {
        int gpy = PY0 + mw * 8 + mi * 2;
        int gxx = PX0 + r0;
#pragma unroll
        for (int ni = 0; ni < 4; ni++) {
            int co_c = co0 + nw * 32 + ni * 8 + c0;
            float* p = out + ((size_t)b * CC + co_c) * HHW + gpy * 80 + gxx;
            p[0]        = acc[mi][ni][0];
            p[HHW]      = acc[mi][ni][1];
            p[80]       = acc[mi][ni][2];
            p[HHW + 80] = acc[mi][ni][3];
        }
    }
}

// ---------------- GroupNorm stats: one block per (b, group), 512 thr ----------------
__global__ __launch_bounds__(512)
void gn_stats_kernel(const float* __restrict__ in, float* __restrict__ mean,
                     float* __restrict__ rstd)
{
    const int bg = blockIdx.x;
    const float4* p = (const float4*)(in + (size_t)bg * (CPG * HHW));
    const int tid = threadIdx.x;
    float s = 0.0f, ss = 0.0f;
#pragma unroll 5
    for (int i = tid; i < CPG * HHW / 4; i += 512) {
        float4 v = p[i];
        s += v.x + v.y + v.z + v.w;
        ss = fmaf(v.x, v.x, ss); ss = fmaf(v.y, v.y, ss);
        ss = fmaf(v.z, v.z, ss); ss = fmaf(v.w, v.w, ss);
    }
    __shared__ float sb0[16], sb1[16];
#pragma unroll
    for (int o = 16; o; o >>= 1) {
        s  += __shfl_down_sync(0xffffffffu, s, o);
        ss += __shfl_down_sync(0xffffffffu, ss, o);
    }
    if ((tid & 31) == 0) { sb0[tid >> 5] = s; sb1[tid >> 5] = ss; }
    __syncthreads();
    if (tid == 0) {
        s = 0.0f; ss = 0.0f;
#pragma unroll
        for (int i = 0; i < 16; i++) { s += sb0[i]; ss += sb1[i]; }
        const float inv_n = 1.0f / (float)(CPG * HHW);
        float m = s * inv_n;
        float var = ss * inv_n - m * m;
        mean[bg] = m;
        rstd[bg] = rsqrtf(var + 1e-5f);
    }
}

// ---------------- spatial gate ----------------
__global__ __launch_bounds__(256)
void gate_kernel(const float* __restrict__ x, const float* __restrict__ gw,
                 const float* __restrict__ gb, float* __restrict__ gate)
{
    __shared__ float wsm[CC];
    const int tid = threadIdx.x;
    wsm[tid] = gw[tid];
    __syncthreads();
    const int p = blockIdx.x * 256 + tid;
    const int b = p / HHW, pp = p - b * HHW;
    const float* xb = x + (size_t)b * CC * HHW + pp;
    float s = gb[0];
#pragma unroll 8
    for (int c = 0; c < CC; c++) s = fmaf(xb[(size_t)c * HHW], wsm[c], s);
    gate[p] = fmaxf(tanhf(s), 0.0f);
}

// ---------------- final: out = relu(gn2(h)*gate + x) ----------------
__global__ __launch_bounds__(256)
void final_kernel(const float* __restrict__ h, const float* __restrict__ mean,
                  const float* __restrict__ rstd, const float* __restrict__ w,
                  const float* __restrict__ bias, const float* __restrict__ gate,
                  const float* __restrict__ x, float* __restrict__ out)
{
    int idx = blockIdx.x * blockDim.x + threadIdx.x;
    if (idx >= TOTAL / 4) return;
    const int c  = (idx / (HHW / 4)) % CC;
    const int b  = idx / ((HHW / 4) * CC);
    const int bg = b * GROUPS + c / CPG;
    const float sc = rstd[bg] * w[c];
    const float sb = fmaf(-mean[bg], sc, bias[c]);
    const int p4 = idx % (HHW / 4);
    const float4 g4 = ((const float4*)(gate + (size_t)b * HHW))[p4];
    float4 hv = ((const float4*)h)[idx];
    float4 xv = ((const float4*)x)[idx];
    float4 o;
    o.x = fmaxf(fmaf(fmaf(hv.x, sc, sb), g4.x, xv.x), 0.0f);
    o.y = fmaxf(fmaf(fmaf(hv.y, sc, sb), g4.y, xv.y), 0.0f);
    o.z = fmaxf(fmaf(fmaf(hv.z, sc, sb), g4.z, xv.z), 0.0f);
    o.w = fmaxf(fmaf(fmaf(hv.w, sc, sb), g4.w, xv.w), 0.0f);
    ((float4*)out)[idx] = o;
}

// ---------------- launch ----------------
extern "C" void kernel_launch(void* const* d_in, const int* in_sizes, int n_in,
                              void* d_out, int out_size)
{
    const float* x    = (const float*)d_in[0];
    const float* w1   = (const float*)d_in[1];
    const float* gn1w = (const float*)d_in[2];
    const float* gn1b = (const float*)d_in[3];
    const float* w2   = (const float*)d_in[4];
    const float* gn2w = (const float*)d_in[5];
    const float* gn2b = (const float*)d_in[6];
    const float* gw   = (const float*)d_in[7];
    const float* gb   = (const float*)d_in[8];
    float* out = (float*)d_out;

    __half* padb; uint2* wtb; float *hb, *gateb, *meanb, *rstdb;
    cudaGetSymbolAddress((void**)&padb,  g_padh);
    cudaGetSymbolAddress((void**)&wtb,   g_wtH);
    cudaGetSymbolAddress((void**)&hb,    g_h);
    cudaGetSymbolAddress((void**)&gateb, g_gate);
    cudaGetSymbolAddress((void**)&meanb, g_mean);
    cudaGetSymbolAddress((void**)&rstdb, g_rstd);

    const int SMEM = NSTG * STAGE;   // 96 KB
    cudaFuncSetAttribute(conv_mma_kernel,
                         cudaFuncAttributeMaxDynamicSharedMemorySize, SMEM);

    const int wN  = 2 * NCHUNK * 2048;
    const int wBl = (wN + 255) / 256;
    const int ewBl = (TOTAL / 4 + 255) / 256;
    dim3 cgrid(10, 5, BB * 2);        // px-tiles x py-tiles x (b, co-half)
    dim3 pgrid(80, 8, BB);            // y x ci-slab x b
    dim3 zgrid(82, 4, BB);            // border strips

    zero_border_kernel<<<zgrid, 256>>>(padb);
    prep_w_kernel<<<wBl, 256>>>(w1, wtb);
    pad_x_t_kernel<<<pgrid, 256>>>(x, padb);
    // conv1 -> g_h (NCHW fp32)
    conv_mma_kernel<<<cgrid, 256, SMEM>>>(padb, wtb, hb);
    // GN1 stats -> padded relu(gn1(h)) channels-last fp16; prep w2
    gn_stats_kernel<<<BB * GROUPS, 512>>>(hb, meanb, rstdb);
    pad_h_t_kernel<<<pgrid, 256>>>(hb, meanb, rstdb, gn1w, gn1b, padb);
    prep_w_kernel<<<wBl, 256>>>(w2, wtb);
    // conv2 -> g_h, GN2 stats
    conv_mma_kernel<<<cgrid, 256, SMEM>>>(padb, wtb, hb);
    gn_stats_kernel<<<BB * GROUPS, 512>>>(hb, meanb, rstdb);
    // gate + fused epilogue
    gate_kernel<<<(BB * HHW) / 256, 256>>>(x, gw, gb, gateb);
    final_kernel<<<ewBl, 256>>>(hb, meanb, rstdb, gn2w, gn2b, gateb, x, out);
}

// round 14
// speedup vs baseline: 1.1294x; 1.1294x over previous
#include <cuda_runtime.h>
#include <cuda_fp16.h>
#include <cstdint>

// ---------------- problem constants ----------------
#define BB 8
#define CC 256
#define HHW 6400          // 80*80
#define GROUPS 32
#define CPG 8
#define TOTAL (BB*CC*HHW) // 13,107,200
#define PW 82
#define PHW (PW*PW)       // 6724
#define NCHUNK 72         // K chunks of 32, tap-major: k = t*256 + ci
#define NSTG 6            // cp.async pipeline stages
#define STAGE 16384       // bytes per stage: A 8KB + B 8KB
#define GN_INVN (1.0f/51200.0f)

// ---------------- scratch (__device__ globals; no allocation) ----------------
__device__ __half g_padh[(size_t)BB * PHW * CC];     // channels-last padded input, fp16
__device__ uint2  g_wtH[(size_t)2 * NCHUNK * 1024];  // weights fp16 fragment-linear
__device__ float  g_h[(size_t)TOTAL];                // conv output, NCHW fp32
__device__ float  g_gate[BB*HHW];
__device__ float  g_stats[1024];                     // [set(2)][sum/ssum(2)][256]

// ---------------- helpers ----------------
__device__ __forceinline__ void mma_f16(float* d, const uint32_t* a, const uint32_t* b){
    asm volatile(
        "mma.sync.aligned.m16n8k16.row.col.f32.f16.f16.f32 "
        "{%0,%1,%2,%3}, {%4,%5,%6,%7}, {%8,%9}, {%0,%1,%2,%3};"
        : "+f"(d[0]), "+f"(d[1]), "+f"(d[2]), "+f"(d[3])
        : "r"(a[0]), "r"(a[1]), "r"(a[2]), "r"(a[3]), "r"(b[0]), "r"(b[1]));
}
__device__ __forceinline__ void cp_async16(uint32_t dst, const void* src){
    asm volatile("cp.async.cg.shared.global [%0], [%1], 16;" :: "r"(dst), "l"(src));
}
__device__ __forceinline__ void ldmatrix4(uint32_t* r, uint32_t addr){
    asm volatile("ldmatrix.sync.aligned.m8n8.x4.shared.b16 {%0,%1,%2,%3}, [%4];"
        : "=r"(r[0]), "=r"(r[1]), "=r"(r[2]), "=r"(r[3]) : "r"(addr));
}

// ---------------- prep kernels ----------------
// weights -> fp16 B-fragment-linear per (half, chunk of 32 k)  [same as R12]
__global__ __launch_bounds__(256)
void prep_w_kernel(const float* __restrict__ w, uint2* __restrict__ wtH)
{
    int i = blockIdx.x * 256 + threadIdx.x;
    if (i >= 2 * NCHUNK * 1024) return;
    int lane = i & 31;
    int kt   = (i >> 5) & 1;
    int nt   = (i >> 6) & 15;
    int rest = i >> 10;                 // half*NCHUNK + ch
    int ch   = rest % NCHUNK;
    int half = rest / NCHUNK;
    int co = half * 128 + nt * 8 + (lane >> 2);
    int t  = ch >> 3;
    int kb = (ch & 7) * 32 + kt * 16 + 2 * (lane & 3);
    const float* wp = w + (size_t)co * CC * 9 + t;
    __half2 lo = __halves2half2(__float2half_rn(wp[(size_t)(kb    ) * 9]),
                                __float2half_rn(wp[(size_t)(kb + 1) * 9]));
    __half2 hi = __halves2half2(__float2half_rn(wp[(size_t)(kb + 8) * 9]),
                                __float2half_rn(wp[(size_t)(kb + 9) * 9]));
    uint2 v;
    v.x = *(uint32_t*)&lo;
    v.y = *(uint32_t*)&hi;
    wtH[i] = v;
}

// zero border ring of padded fp16 buffer + the GN stat accumulators
__global__ __launch_bounds__(256)
void zero_border_kernel(__half* __restrict__ pad, float* __restrict__ stats)
{
    int pos = blockIdx.x;       // 0..81
    int s   = blockIdx.y;
    int b   = blockIdx.z;
    if (pos == 0 && s == 0 && b == 0) {
        // one block also zeroes the stats accumulators (1024 floats)
    }
    if (blockIdx.x == 0 && blockIdx.y == 0 && blockIdx.z == 0) {
#pragma unroll
        for (int i = threadIdx.x; i < 1024; i += 256) stats[i] = 0.0f;
    }
    int py, px;
    if (s == 0)      { py = 0;   px = pos; }
    else if (s == 1) { py = 81;  px = pos; }
    else if (s == 2) { py = pos; px = 0;   }
    else             { py = pos; px = 81;  }
    pad[((size_t)b * PHW + py * PW + px) * CC + threadIdx.x] = __float2half_rn(0.0f);
}

// NCHW x -> channels-last padded fp16
__global__ __launch_bounds__(256)
void pad_x_t_kernel(const float* __restrict__ x, __half* __restrict__ pad)
{
    __shared__ float t[32 * 81];
    const int y   = blockIdx.x;
    const int cB  = blockIdx.y;
    const int b   = blockIdx.z;
    const int tid = threadIdx.x;
    for (int idx = tid; idx < 2560; idx += 256) {
        int px = idx % 80, cc = idx / 80;
        t[cc * 81 + px] = x[((size_t)(b * CC + cB * 32 + cc) * 80 + y) * 80 + px];
    }
    __syncthreads();
    for (int idx = tid; idx < 2560; idx += 256) {
        int cc = idx & 31, px = idx >> 5;
        pad[((size_t)b * PHW + (y + 1) * PW + (px + 1)) * CC + cB * 32 + cc] =
            __float2half_rn(t[cc * 81 + px]);
    }
}

// NCHW h -> GN affine (from fused sums) + ReLU -> channels-last padded fp16
__global__ __launch_bounds__(256)
void pad_h_t_kernel(const float* __restrict__ h, const float* __restrict__ sums,
                    const float* __restrict__ gw, const float* __restrict__ gb,
                    __half* __restrict__ pad)
{
    __shared__ float t[32 * 81];
    __shared__ float ssc[32], ssb[32];
    const int y   = blockIdx.x;
    const int cB  = blockIdx.y;
    const int b   = blockIdx.z;
    const int tid = threadIdx.x;
    if (tid < 32) {
        int ci = cB * 32 + tid;
        int bg = b * GROUPS + (ci >> 3);
        float m   = sums[bg] * GN_INVN;
        float var = sums[256 + bg] * GN_INVN - m * m;
        float rs  = rsqrtf(var + 1e-5f);
        float sc = rs * gw[ci];
        ssc[tid] = sc;
        ssb[tid] = fmaf(-m, sc, gb[ci]);
    }
    for (int idx = tid; idx < 2560; idx += 256) {
        int px = idx % 80, cc = idx / 80;
        t[cc * 81 + px] = h[((size_t)(b * CC + cB * 32 + cc) * 80 + y) * 80 + px];
    }
    __syncthreads();
    for (int idx = tid; idx < 2560; idx += 256) {
        int cc = idx & 31, px = idx >> 5;
        float v = fmaxf(fmaf(t[cc * 81 + px], ssc[cc], ssb[cc]), 0.0f);
        pad[((size_t)b * PHW + (y + 1) * PW + (px + 1)) * CC + cB * 32 + cc] =
            __float2half_rn(v);
    }
}

// ---------------- fp16 HMMA implicit-GEMM conv, cp.async 6-stage, chunk=32 ----------------
// 256 thr = 8 warps (2M x 4N), warp tile 64px x 32co. CTA tile 128px x 128co.
// Stage: A plane-major [kk(4)][px(128)][16B] 8KB + B fragment-linear 8KB.
// Epilogue also accumulates GN partial sums (sum, sumsq) per (b, group) via atomics.
__global__ __launch_bounds__(256, 2)
void conv_mma_kernel(const __half* __restrict__ pad, const uint2* __restrict__ wtH,
                     float* __restrict__ out, float* __restrict__ sums)
{
    extern __shared__ char dsm[];
    __shared__ int s_toff[9];

    const int tid  = threadIdx.x;
    const int lane = tid & 31;
    const int warp = tid >> 5;               // 0..7
    const int mw = warp >> 2;                // 0..1
    const int nw = warp & 3;                 // 0..3

    if (tid < 9) s_toff[tid] = ((tid / 3) * PW + (tid % 3)) * CC;

    const int PX0 = blockIdx.x * 8;
    const int PY0 = blockIdx.y * 16;
    const int bz  = blockIdx.z;
    const int b   = bz >> 1;
    const int half = bz & 1;
    const int co0  = half * 128;

    const int pxP  = tid >> 1;
    const int segH = tid & 1;
    const int gy = PY0 + (pxP >> 3);
    const int gx = PX0 + (pxP & 7);
    const __half* Apix = pad + ((size_t)b * PHW + (size_t)gy * PW + gx) * CC;
    const char* Bsrc0 = (const char*)(wtH + (size_t)half * NCHUNK * 1024);
    const uint32_t smem0 = (uint32_t)__cvta_generic_to_shared(dsm);

    const int ltile = lane >> 3;
    const uint32_t lmLane = (uint32_t)((ltile >> 1) * 2048 +
                                       (((ltile & 1) * 8 + (lane & 7)) * 16));

    float acc[4][4][4];
#pragma unroll
    for (int mi = 0; mi < 4; mi++)
#pragma unroll
        for (int ni = 0; ni < 4; ni++)
#pragma unroll
            for (int q = 0; q < 4; q++) acc[mi][ni][q] = 0.0f;

    __syncthreads();   // s_toff ready

#define ISSUE(CH) do {                                                          \
        const int _ch = (CH);                                                   \
        const int _st = _ch % NSTG;                                             \
        const __half* _as = Apix + s_toff[_ch >> 3] + ((_ch & 7) << 5);         \
        uint32_t _base = smem0 + _st * STAGE;                                   \
        _Pragma("unroll")                                                       \
        for (int _j = 0; _j < 2; _j++) {                                        \
            int _kk = segH * 2 + _j;                                            \
            cp_async16(_base + _kk * 2048 + pxP * 16, _as + _kk * 8);           \
        }                                                                       \
        const char* _bs = Bsrc0 + (size_t)_ch * 8192 + tid * 32;                \
        uint32_t _bd = _base + 8192 + tid * 32;                                 \
        cp_async16(_bd,      _bs);                                              \
        cp_async16(_bd + 16, _bs + 16);                                         \
        asm volatile("cp.async.commit_group;" ::: "memory");                    \
    } while (0)

    // prologue: stages 0..4
    ISSUE(0); ISSUE(1); ISSUE(2); ISSUE(3); ISSUE(4);

    for (int ch = 0; ch < NCHUNK; ch++) {
        if (ch < NCHUNK - 4)
            asm volatile("cp.async.wait_group 4;" ::: "memory");
        else if (ch == NCHUNK - 4)
            asm volatile("cp.async.wait_group 3;" ::: "memory");
        else if (ch == NCHUNK - 3)
            asm volatile("cp.async.wait_group 2;" ::: "memory");
        else if (ch == NCHUNK - 2)
            asm volatile("cp.async.wait_group 1;" ::: "memory");
        else
            asm volatile("cp.async.wait_group 0;" ::: "memory");
        __syncthreads();

        const int st = ch % NSTG;
        const uint32_t Abase = smem0 + st * STAGE;
        const uint2* Bs = (const uint2*)(dsm + st * STAGE + 8192);

#pragma unroll
        for (int kt = 0; kt < 2; kt++) {
            uint32_t af[4][4];
            uint2 bf[4];
            const uint32_t kbase = Abase + kt * 4096 + lmLane;
#pragma unroll
            for (int mi = 0; mi < 4; mi++)
                ldmatrix4(af[mi], kbase + (uint32_t)((mw * 64 + mi * 16) * 16));
#pragma unroll
            for (int ni = 0; ni < 4; ni++)
                bf[ni] = Bs[(nw * 4 + ni) * 64 + kt * 32 + lane];
#pragma unroll
            for (int mi = 0; mi < 4; mi++)
#pragma unroll
                for (int ni = 0; ni < 4; ni++)
                    mma_f16(acc[mi][ni], af[mi], (const uint32_t*)&bf[ni]);
        }

        if (ch + 5 < NCHUNK) ISSUE(ch + 5);
    }
#undef ISSUE

    // ---- epilogue: store + fused GN partial sums ----
    const int r0 = lane >> 2;
    const int c0 = 2 * (lane & 3);
#pragma unroll
    for (int mi = 0; mi < 4; mi++) {
        int gpy = PY0 + mw * 8 + mi * 2;
        int gxx = PX0 + r0;
#pragma unroll
        for (int ni = 0; ni < 4; ni++) {
            int co_c = co0 + nw * 32 + ni * 8 + c0;
            float* p = out + ((size_t)b * CC + co_c) * HHW + gpy * 80 + gxx;
            p[0]        = acc[mi][ni][0];
            p[HHW]      = acc[mi][ni][1];
            p[80]       = acc[mi][ni][2];
            p[HHW + 80] = acc[mi][ni][3];
        }
    }
    // per-ni group partials: group = half*16 + nw*4 + ni (co_c and co_c+1 same group)
#pragma unroll
    for (int ni = 0; ni < 4; ni++) {
        float s = 0.0f, ss = 0.0f;
#pragma unroll
        for (int mi = 0; mi < 4; mi++)
#pragma unroll
            for (int q = 0; q < 4; q++) {
                float v = acc[mi][ni][q];
                s += v;
                ss = fmaf(v, v, ss);
            }
#pragma unroll
        for (int o = 16; o; o >>= 1) {
            s  += __shfl_down_sync(0xffffffffu, s, o);
            ss += __shfl_down_sync(0xffffffffu, ss, o);
        }
        if (lane == 0) {
            int bg = b * GROUPS + half * 16 + nw * 4 + ni;
            atomicAdd(&sums[bg], s);
            atomicAdd(&sums[256 + bg], ss);
        }
    }
}

// ---------------- spatial gate: warp per pixel, fp16 channels-last input ----------------
__global__ __launch_bounds__(256)
void gate_kernel(const __half* __restrict__ padh, const float* __restrict__ gw,
                 const float* __restrict__ gb, float* __restrict__ gate)
{
    __shared__ float wsm[CC];
    const int tid = threadIdx.x;
    wsm[tid] = gw[tid];
    __syncthreads();
    const int lane = tid & 31;
    const int p = blockIdx.x * 8 + (tid >> 5);     // pixel index
    const int b = p / HHW, pp = p - b * HHW;
    const int y = pp / 80, x = pp - (pp / 80) * 80;
    const __half* xp = padh + ((size_t)b * PHW + (y + 1) * PW + (x + 1)) * CC + lane * 8;
    uint4 v = *(const uint4*)xp;
    const __half2* h2 = (const __half2*)&v;
    float s = 0.0f;
#pragma unroll
    for (int j = 0; j < 4; j++) {
        float2 f = __half22float2(h2[j]);
        s = fmaf(f.x, wsm[lane * 8 + 2 * j], s);
        s = fmaf(f.y, wsm[lane * 8 + 2 * j + 1], s);
    }
#pragma unroll
    for (int o = 16; o; o >>= 1) s += __shfl_down_sync(0xffffffffu, s, o);
    if (lane == 0) gate[p] = fmaxf(tanhf(s + gb[0]), 0.0f);
}

// ---------------- final: out = relu(gn2(h)*gate + x), stats from sums ----------------
__global__ __launch_bounds__(256)
void final_kernel(const float* __restrict__ h, const float* __restrict__ sums,
                  const float* __restrict__ w, const float* __restrict__ bias,
                  const float* __restrict__ gate, const float* __restrict__ x,
                  float* __restrict__ out)
{
    int idx = blockIdx.x * blockDim.x + threadIdx.x;
    if (idx >= TOTAL / 4) return;
    const int c  = (idx / (HHW / 4)) % CC;
    const int b  = idx / ((HHW / 4) * CC);
    const int bg = b * GROUPS + (c >> 3);
    const float m   = sums[bg] * GN_INVN;
    const float var = sums[256 + bg] * GN_INVN - m * m;
    const float rs  = rsqrtf(var + 1e-5f);
    const float sc = rs * w[c];
    const float sb = fmaf(-m, sc, bias[c]);
    const int p4 = idx % (HHW / 4);
    const float4 g4 = ((const float4*)(gate + (size_t)b * HHW))[p4];
    float4 hv = ((const float4*)h)[idx];
    float4 xv = ((const float4*)x)[idx];
    float4 o;
    o.x = fmaxf(fmaf(fmaf(hv.x, sc, sb), g4.x, xv.x), 0.0f);
    o.y = fmaxf(fmaf(fmaf(hv.y, sc, sb), g4.y, xv.y), 0.0f);
    o.z = fmaxf(fmaf(fmaf(hv.z, sc, sb), g4.z, xv.z), 0.0f);
    o.w = fmaxf(fmaf(fmaf(hv.w, sc, sb), g4.w, xv.w), 0.0f);
    ((float4*)out)[idx] = o;
}

// ---------------- launch ----------------
extern "C" void kernel_launch(void* const* d_in, const int* in_sizes, int n_in,
                              void* d_out, int out_size)
{
    const float* x    = (const float*)d_in[0];
    const float* w1   = (const float*)d_in[1];
    const float* gn1w = (const float*)d_in[2];
    const float* gn1b = (const float*)d_in[3];
    const float* w2   = (const float*)d_in[4];
    const float* gn2w = (const float*)d_in[5];
    const float* gn2b = (const float*)d_in[6];
    const float* gw   = (const float*)d_in[7];
    const float* gb   = (const float*)d_in[8];
    float* out = (float*)d_out;

    __half* padb; uint2* wtb; float *hb, *gateb, *statsb;
    cudaGetSymbolAddress((void**)&padb,   g_padh);
    cudaGetSymbolAddress((void**)&wtb,    g_wtH);
    cudaGetSymbolAddress((void**)&hb,     g_h);
    cudaGetSymbolAddress((void**)&gateb,  g_gate);
    cudaGetSymbolAddress((void**)&statsb, g_stats);

    const int SMEM = NSTG * STAGE;   // 96 KB
    cudaFuncSetAttribute(conv_mma_kernel,
                         cudaFuncAttributeMaxDynamicSharedMemorySize, SMEM);

    const int wN  = 2 * NCHUNK * 1024;
    const int wBl = (wN + 255) / 256;
    const int ewBl = (TOTAL / 4 + 255) / 256;
    dim3 cgrid(10, 5, BB * 2);        // px-tiles x py-tiles x (b, co-half)
    dim3 pgrid(80, 8, BB);            // y x ci-slab x b
    dim3 zgrid(82, 4, BB);            // border strips

    zero_border_kernel<<<zgrid, 256>>>(padb, statsb);          // + zero stats
    prep_w_kernel<<<wBl, 256>>>(w1, wtb);
    pad_x_t_kernel<<<pgrid, 256>>>(x, padb);
    // conv1 -> g_h, stats set0
    conv_mma_kernel<<<cgrid, 256, SMEM>>>(padb, wtb, hb, statsb);
    // gate from original fp16 x (must precede pad_h_t which overwrites padb)
    gate_kernel<<<(BB * HHW) / 8, 256>>>(padb, gw, gb, gateb);
    // padded relu(gn1(h)) channels-last fp16 from fused stats; prep w2
    pad_h_t_kernel<<<pgrid, 256>>>(hb, statsb, gn1w, gn1b, padb);
    prep_w_kernel<<<wBl, 256>>>(w2, wtb);
    // conv2 -> g_h, stats set1
    conv_mma_kernel<<<cgrid, 256, SMEM>>>(padb, wtb, hb, statsb + 512);
    // fused epilogue
    final_kernel<<<ewBl, 256>>>(hb, statsb + 512, gn2w, gn2b, gateb, x, out);
}

// round 15
// speedup vs baseline: 1.1955x; 1.0585x over previous
#include <cuda_runtime.h>
#include <cuda_fp16.h>
#include <cstdint>

// ---------------- problem constants ----------------
#define BB 8
#define CC 256
#define HHW 6400          // 80*80
#define GROUPS 32
#define CPG 8
#define TOTAL (BB*CC*HHW) // 13,107,200
#define PW 82
#define PHW (PW*PW)       // 6724
#define NCHUNK 72         // K chunks of 32, tap-major: k = t*256 + ci
#define NSTG 7            // cp.async pipeline stages (112KB)
#define STAGE 16384       // bytes per stage: A 8KB + B 8KB
#define GN_INVN (1.0f/51200.0f)

// ---------------- scratch (__device__ globals; no allocation) ----------------
__device__ __half g_padh[(size_t)BB * PHW * CC];     // channels-last padded input, fp16
__device__ uint2  g_wtH[(size_t)2 * NCHUNK * 1024];  // weights fp16 fragment-linear
__device__ float  g_h[(size_t)TOTAL];                // conv output, NCHW fp32
__device__ float  g_gate[BB*HHW];
__device__ float  g_stats[1024];                     // [set(2)][sum/ssum(2)][256]

// ---------------- helpers ----------------
__device__ __forceinline__ void mma_f16(float* d, const uint32_t* a, const uint32_t* b){
    asm volatile(
        "mma.sync.aligned.m16n8k16.row.col.f32.f16.f16.f32 "
        "{%0,%1,%2,%3}, {%4,%5,%6,%7}, {%8,%9}, {%0,%1,%2,%3};"
        : "+f"(d[0]), "+f"(d[1]), "+f"(d[2]), "+f"(d[3])
        : "r"(a[0]), "r"(a[1]), "r"(a[2]), "r"(a[3]), "r"(b[0]), "r"(b[1]));
}
__device__ __forceinline__ void cp_async16(uint32_t dst, const void* src){
    asm volatile("cp.async.cg.shared.global [%0], [%1], 16;" :: "r"(dst), "l"(src));
}
__device__ __forceinline__ void ldmatrix4(uint32_t* r, uint32_t addr){
    asm volatile("ldmatrix.sync.aligned.m8n8.x4.shared.b16 {%0,%1,%2,%3}, [%4];"
        : "=r"(r[0]), "=r"(r[1]), "=r"(r[2]), "=r"(r[3]) : "r"(addr));
}

// ---------------- prep kernels ----------------
// weights -> fp16 B-fragment-linear per (half, chunk of 32 k)
__global__ __launch_bounds__(256)
void prep_w_kernel(const float* __restrict__ w, uint2* __restrict__ wtH)
{
    int i = blockIdx.x * 256 + threadIdx.x;
    if (i >= 2 * NCHUNK * 1024) return;
    int lane = i & 31;
    int kt   = (i >> 5) & 1;
    int nt   = (i >> 6) & 15;
    int rest = i >> 10;                 // half*NCHUNK + ch
    int ch   = rest % NCHUNK;
    int half = rest / NCHUNK;
    int co = half * 128 + nt * 8 + (lane >> 2);
    int t  = ch >> 3;
    int kb = (ch & 7) * 32 + kt * 16 + 2 * (lane & 3);
    const float* wp = w + (size_t)co * CC * 9 + t;
    __half2 lo = __halves2half2(__float2half_rn(wp[(size_t)(kb    ) * 9]),
                                __float2half_rn(wp[(size_t)(kb + 1) * 9]));
    __half2 hi = __halves2half2(__float2half_rn(wp[(size_t)(kb + 8) * 9]),
                                __float2half_rn(wp[(size_t)(kb + 9) * 9]));
    uint2 v;
    v.x = *(uint32_t*)&lo;
    v.y = *(uint32_t*)&hi;
    wtH[i] = v;
}

// zero border ring + stats accumulators
__global__ __launch_bounds__(256)
void zero_border_kernel(__half* __restrict__ pad, float* __restrict__ stats)
{
    int pos = blockIdx.x;       // 0..81
    int s   = blockIdx.y;
    int b   = blockIdx.z;
    if (blockIdx.x == 0 && blockIdx.y == 0 && blockIdx.z == 0) {
#pragma unroll
        for (int i = threadIdx.x; i < 1024; i += 256) stats[i] = 0.0f;
    }
    int py, px;
    if (s == 0)      { py = 0;   px = pos; }
    else if (s == 1) { py = 81;  px = pos; }
    else if (s == 2) { py = pos; px = 0;   }
    else             { py = pos; px = 81;  }
    pad[((size_t)b * PHW + py * PW + px) * CC + threadIdx.x] = __float2half_rn(0.0f);
}

// NCHW x -> channels-last padded fp16
__global__ __launch_bounds__(256)
void pad_x_t_kernel(const float* __restrict__ x, __half* __restrict__ pad)
{
    __shared__ float t[32 * 81];
    const int y   = blockIdx.x;
    const int cB  = blockIdx.y;
    const int b   = blockIdx.z;
    const int tid = threadIdx.x;
    for (int idx = tid; idx < 2560; idx += 256) {
        int px = idx % 80, cc = idx / 80;
        t[cc * 81 + px] = x[((size_t)(b * CC + cB * 32 + cc) * 80 + y) * 80 + px];
    }
    __syncthreads();
    for (int idx = tid; idx < 2560; idx += 256) {
        int cc = idx & 31, px = idx >> 5;
        pad[((size_t)b * PHW + (y + 1) * PW + (px + 1)) * CC + cB * 32 + cc] =
            __float2half_rn(t[cc * 81 + px]);
    }
}

// NCHW h -> GN affine (from fused sums) + ReLU -> channels-last padded fp16
__global__ __launch_bounds__(256)
void pad_h_t_kernel(const float* __restrict__ h, const float* __restrict__ sums,
                    const float* __restrict__ gw, const float* __restrict__ gb,
                    __half* __restrict__ pad)
{
    __shared__ float t[32 * 81];
    __shared__ float ssc[32], ssb[32];
    const int y   = blockIdx.x;
    const int cB  = blockIdx.y;
    const int b   = blockIdx.z;
    const int tid = threadIdx.x;
    if (tid < 32) {
        int ci = cB * 32 + tid;
        int bg = b * GROUPS + (ci >> 3);
        float m   = sums[bg] * GN_INVN;
        float var = sums[256 + bg] * GN_INVN - m * m;
        float rs  = rsqrtf(var + 1e-5f);
        float sc = rs * gw[ci];
        ssc[tid] = sc;
        ssb[tid] = fmaf(-m, sc, gb[ci]);
    }
    for (int idx = tid; idx < 2560; idx += 256) {
        int px = idx % 80, cc = idx / 80;
        t[cc * 81 + px] = h[((size_t)(b * CC + cB * 32 + cc) * 80 + y) * 80 + px];
    }
    __syncthreads();
    for (int idx = tid; idx < 2560; idx += 256) {
        int cc = idx & 31, px = idx >> 5;
        float v = fmaxf(fmaf(t[cc * 81 + px], ssc[cc], ssb[cc]), 0.0f);
        pad[((size_t)b * PHW + (y + 1) * PW + (px + 1)) * CC + cB * 32 + cc] =
            __float2half_rn(v);
    }
}

// ---------------- fp16 HMMA implicit-GEMM conv, 7-stage, 2 chunks per barrier ----------------
// 256 thr = 8 warps (2M x 4N), warp tile 64px x 32co. CTA tile 128px x 128co.
// Stage: A plane-major [kk(4)][px(128)][16B] 8KB + B fragment-linear 8KB.
__global__ __launch_bounds__(256, 2)
void conv_mma_kernel(const __half* __restrict__ pad, const uint2* __restrict__ wtH,
                     float* __restrict__ out, float* __restrict__ sums)
{
    extern __shared__ char dsm[];
    __shared__ int s_toff[9];

    const int tid  = threadIdx.x;
    const int lane = tid & 31;
    const int warp = tid >> 5;               // 0..7
    const int mw = warp >> 2;                // 0..1
    const int nw = warp & 3;                 // 0..3

    if (tid < 9) s_toff[tid] = ((tid / 3) * PW + (tid % 3)) * CC;

    const int PX0 = blockIdx.x * 8;
    const int PY0 = blockIdx.y * 16;
    const int bz  = blockIdx.z;
    const int b   = bz >> 1;
    const int half = bz & 1;
    const int co0  = half * 128;

    const int pxP  = tid >> 1;
    const int segH = tid & 1;
    const int gy = PY0 + (pxP >> 3);
    const int gx = PX0 + (pxP & 7);
    const __half* Apix = pad + ((size_t)b * PHW + (size_t)gy * PW + gx) * CC;
    const char* Bsrc0 = (const char*)(wtH + (size_t)half * NCHUNK * 1024);
    const uint32_t smem0 = (uint32_t)__cvta_generic_to_shared(dsm);

    const int ltile = lane >> 3;
    const uint32_t lmLane = (uint32_t)((ltile >> 1) * 2048 +
                                       (((ltile & 1) * 8 + (lane & 7)) * 16));

    float acc[4][4][4];
#pragma unroll
    for (int mi = 0; mi < 4; mi++)
#pragma unroll
        for (int ni = 0; ni < 4; ni++)
#pragma unroll
            for (int q = 0; q < 4; q++) acc[mi][ni][q] = 0.0f;

    __syncthreads();   // s_toff ready

// issue chunk CH into stage ST
#define ISSUE(CH, ST) do {                                                      \
        const int _ch = (CH);                                                   \
        const __half* _as = Apix + s_toff[_ch >> 3] + ((_ch & 7) << 5);         \
        uint32_t _base = smem0 + (ST) * STAGE;                                  \
        _Pragma("unroll")                                                       \
        for (int _j = 0; _j < 2; _j++) {                                        \
            int _kk = segH * 2 + _j;                                            \
            cp_async16(_base + _kk * 2048 + pxP * 16, _as + _kk * 8);           \
        }                                                                       \
        const char* _bs = Bsrc0 + (size_t)_ch * 8192 + tid * 32;                \
        uint32_t _bd = _base + 8192 + tid * 32;                                 \
        cp_async16(_bd,      _bs);                                              \
        cp_async16(_bd + 16, _bs + 16);                                         \
        asm volatile("cp.async.commit_group;" ::: "memory");                    \
    } while (0)

// consume one chunk from stage ST
#define CONSUME(ST) do {                                                        \
        const uint32_t Abase = smem0 + (ST) * STAGE;                            \
        const uint2* Bs = (const uint2*)(dsm + (ST) * STAGE + 8192);            \
        _Pragma("unroll")                                                       \
        for (int kt = 0; kt < 2; kt++) {                                        \
            uint32_t af[4][4];                                                  \
            uint2 bf[4];                                                        \
            const uint32_t kbase = Abase + kt * 4096 + lmLane;                  \
            _Pragma("unroll")                                                   \
            for (int mi = 0; mi < 4; mi++)                                      \
                ldmatrix4(af[mi], kbase + (uint32_t)((mw * 64 + mi * 16) * 16));\
            _Pragma("unroll")                                                   \
            for (int ni = 0; ni < 4; ni++)                                      \
                bf[ni] = Bs[(nw * 4 + ni) * 64 + kt * 32 + lane];               \
            _Pragma("unroll")                                                   \
            for (int mi = 0; mi < 4; mi++)                                      \
                _Pragma("unroll")                                               \
                for (int ni = 0; ni < 4; ni++)                                  \
                    mma_f16(acc[mi][ni], af[mi], (const uint32_t*)&bf[ni]);     \
        }                                                                       \
    } while (0)

    // prologue: chunks 0..4 -> stages 0..4
    ISSUE(0, 0); ISSUE(1, 1); ISSUE(2, 2); ISSUE(3, 3); ISSUE(4, 4);

    // paired mainloop: 36 barriers, consume 2 chunks per barrier
    for (int ch = 0; ch < NCHUNK; ch += 2) {
        if (ch < 68)
            asm volatile("cp.async.wait_group 3;" ::: "memory");
        else if (ch == 68)
            asm volatile("cp.async.wait_group 2;" ::: "memory");
        else
            asm volatile("cp.async.wait_group 0;" ::: "memory");
        __syncthreads();

        const int s0 = ch % NSTG;
        const int s1 = (ch + 1) % NSTG;

        CONSUME(s0);
        if (ch + 5 < NCHUNK) ISSUE(ch + 5, (ch + 5) % NSTG);
        CONSUME(s1);
        if (ch + 6 < NCHUNK) ISSUE(ch + 6, (ch + 6) % NSTG);
    }
#undef ISSUE
#undef CONSUME

    // ---- epilogue: store + fused GN partial sums ----
    const int r0 = lane >> 2;
    const int c0 = 2 * (lane & 3);
#pragma unroll
    for (int mi = 0; mi < 4; mi++) {
        int gpy = PY0 + mw * 8 + mi * 2;
        int gxx = PX0 + r0;
#pragma unroll
        for (int ni = 0; ni < 4; ni++) {
            int co_c = co0 + nw * 32 + ni * 8 + c0;
            float* p = out + ((size_t)b * CC + co_c) * HHW + gpy * 80 + gxx;
            p[0]        = acc[mi][ni][0];
            p[HHW]      = acc[mi][ni][1];
            p[80]       = acc[mi][ni][2];
            p[HHW + 80] = acc[mi][ni][3];
        }
    }
#pragma unroll
    for (int ni = 0; ni < 4; ni++) {
        float s = 0.0f, ss = 0.0f;
#pragma unroll
        for (int mi = 0; mi < 4; mi++)
#pragma unroll
            for (int q = 0; q < 4; q++) {
                float v = acc[mi][ni][q];
                s += v;
                ss = fmaf(v, v, ss);
            }
#pragma unroll
        for (int o = 16; o; o >>= 1) {
            s  += __shfl_down_sync(0xffffffffu, s, o);
            ss += __shfl_down_sync(0xffffffffu, ss, o);
        }
        if (lane == 0) {
            int bg = b * GROUPS + half * 16 + nw * 4 + ni;
            atomicAdd(&sums[bg], s);
            atomicAdd(&sums[256 + bg], ss);
        }
    }
}

// ---------------- spatial gate: warp per pixel, fp16 channels-last input ----------------
__global__ __launch_bounds__(256)
void gate_kernel(const __half* __restrict__ padh, const float* __restrict__ gw,
                 const float* __restrict__ gb, float* __restrict__ gate)
{
    __shared__ float wsm[CC];
    const int tid = threadIdx.x;
    wsm[tid] = gw[tid];
    __syncthreads();
    const int lane = tid & 31;
    const int p = blockIdx.x * 8 + (tid >> 5);     // pixel index
    const int b = p / HHW, pp = p - b * HHW;
    const int y = pp / 80, x = pp - (pp / 80) * 80;
    const __half* xp = padh + ((size_t)b * PHW + (y + 1) * PW + (x + 1)) * CC + lane * 8;
    uint4 v = *(const uint4*)xp;
    const __half2* h2 = (const __half2*)&v;
    float s = 0.0f;
#pragma unroll
    for (int j = 0; j < 4; j++) {
        float2 f = __half22float2(h2[j]);
        s = fmaf(f.x, wsm[lane * 8 + 2 * j], s);
        s = fmaf(f.y, wsm[lane * 8 + 2 * j + 1], s);
    }
#pragma unroll
    for (int o = 16; o; o >>= 1) s += __shfl_down_sync(0xffffffffu, s, o);
    if (lane == 0) gate[p] = fmaxf(tanhf(s + gb[0]), 0.0f);
}

// ---------------- final: out = relu(gn2(h)*gate + x), stats from sums ----------------
__global__ __launch_bounds__(256)
void final_kernel(const float* __restrict__ h, const float* __restrict__ sums,
                  const float* __restrict__ w, const float* __restrict__ bias,
                  const float* __restrict__ gate, const float* __restrict__ x,
                  float* __restrict__ out)
{
    int idx = blockIdx.x * blockDim.x + threadIdx.x;
    if (idx >= TOTAL / 4) return;
    const int c  = (idx / (HHW / 4)) % CC;
    const int b  = idx / ((HHW / 4) * CC);
    const int bg = b * GROUPS + (c >> 3);
    const float m   = sums[bg] * GN_INVN;
    const float var = sums[256 + bg] * GN_INVN - m * m;
    const float rs  = rsqrtf(var + 1e-5f);
    const float sc = rs * w[c];
    const float sb = fmaf(-m, sc, bias[c]);
    const int p4 = idx % (HHW / 4);
    const float4 g4 = ((const float4*)(gate + (size_t)b * HHW))[p4];
    float4 hv = ((const float4*)h)[idx];
    float4 xv = ((const float4*)x)[idx];
    float4 o;
    o.x = fmaxf(fmaf(fmaf(hv.x, sc, sb), g4.x, xv.x), 0.0f);
    o.y = fmaxf(fmaf(fmaf(hv.y, sc, sb), g4.y, xv.y), 0.0f);
    o.z = fmaxf(fmaf(fmaf(hv.z, sc, sb), g4.z, xv.z), 0.0f);
    o.w = fmaxf(fmaf(fmaf(hv.w, sc, sb), g4.w, xv.w), 0.0f);
    ((float4*)out)[idx] = o;
}

// ---------------- launch ----------------
extern "C" void kernel_launch(void* const* d_in, const int* in_sizes, int n_in,
                              void* d_out, int out_size)
{
    const float* x    = (const float*)d_in[0];
    const float* w1   = (const float*)d_in[1];
    const float* gn1w = (const float*)d_in[2];
    const float* gn1b = (const float*)d_in[3];
    const float* w2   = (const float*)d_in[4];
    const float* gn2w = (const float*)d_in[5];
    const float* gn2b = (const float*)d_in[6];
    const float* gw   = (const float*)d_in[7];
    const float* gb   = (const float*)d_in[8];
    float* out = (float*)d_out;

    __half* padb; uint2* wtb; float *hb, *gateb, *statsb;
    cudaGetSymbolAddress((void**)&padb,   g_padh);
    cudaGetSymbolAddress((void**)&wtb,    g_wtH);
    cudaGetSymbolAddress((void**)&hb,     g_h);
    cudaGetSymbolAddress((void**)&gateb,  g_gate);
    cudaGetSymbolAddress((void**)&statsb, g_stats);

    const int SMEM = NSTG * STAGE;   // 112 KB
    cudaFuncSetAttribute(conv_mma_kernel,
                         cudaFuncAttributeMaxDynamicSharedMemorySize, SMEM);

    const int wN  = 2 * NCHUNK * 1024;
    const int wBl = (wN + 255) / 256;
    const int ewBl = (TOTAL / 4 + 255) / 256;
    dim3 cgrid(10, 5, BB * 2);        // px-tiles x py-tiles x (b, co-half)
    dim3 pgrid(80, 8, BB);            // y x ci-slab x b
    dim3 zgrid(82, 4, BB);            // border strips

    zero_border_kernel<<<zgrid, 256>>>(padb, statsb);
    prep_w_kernel<<<wBl, 256>>>(w1, wtb);
    pad_x_t_kernel<<<pgrid, 256>>>(x, padb);
    // conv1 -> g_h, stats set0
    conv_mma_kernel<<<cgrid, 256, SMEM>>>(padb, wtb, hb, statsb);
    // gate from original fp16 x (must precede pad_h_t which overwrites padb)
    gate_kernel<<<(BB * HHW) / 8, 256>>>(padb, gw, gb, gateb);
    // padded relu(gn1(h)) channels-last fp16 from fused stats; prep w2
    pad_h_t_kernel<<<pgrid, 256>>>(hb, statsb, gn1w, gn1b, padb);
    prep_w_kernel<<<wBl, 256>>>(w2, wtb);
    // conv2 -> g_h, stats set1
    conv_mma_kernel<<<cgrid, 256, SMEM>>>(padb, wtb, hb, statsb + 512);
    // fused epilogue
    final_kernel<<<ewBl, 256>>>(hb, statsb + 512, gn2w, gn2b, gateb, x, out);
}